// round 1
// baseline (speedup 1.0000x reference)
#include <cuda_runtime.h>
#include <math.h>

// NeuS importance sampling: one warp per ray, 2 samples per lane.
// N_RAYS = 131072, N_SAMPLES = 64, N_IMP = 64, inv_s = 64 (fixed by setup_inputs).

#define WARPS_PER_BLOCK 8
#define NS 64

__global__ __launch_bounds__(WARPS_PER_BLOCK * 32)
void neus_kernel(const float* __restrict__ rays_o,
                 const float* __restrict__ rays_d,
                 const float* __restrict__ z_vals,
                 const float* __restrict__ sdf,
                 float* __restrict__ out,
                 int n_rays, float inv_s)
{
    const int wib  = threadIdx.x >> 5;
    const int lane = threadIdx.x & 31;
    const int ray  = blockIdx.x * WARPS_PER_BLOCK + wib;
    if (ray >= n_rays) return;   // whole warp exits together (warp-per-ray)

    __shared__ float sh_z  [WARPS_PER_BLOCK][NS];
    __shared__ float sh_s  [WARPS_PER_BLOCK][NS];
    __shared__ float sh_rad[WARPS_PER_BLOCK][NS];
    __shared__ float sh_cdf[WARPS_PER_BLOCK][NS];

    float* shz = sh_z[wib];
    float* shs = sh_s[wib];
    float* shr = sh_rad[wib];
    float* shc = sh_cdf[wib];

    // ---- coalesced loads: 2 consecutive elements per lane ----
    const size_t base = (size_t)ray * NS;
    const float2 zz = reinterpret_cast<const float2*>(z_vals + base)[lane];
    const float2 ss = reinterpret_cast<const float2*>(sdf    + base)[lane];
    shz[2*lane]   = zz.x;  shz[2*lane+1] = zz.y;
    shs[2*lane]   = ss.x;  shs[2*lane+1] = ss.y;

    // ray origin/direction (broadcast loads, same addr per warp)
    const float ox = rays_o[3*ray+0], oy = rays_o[3*ray+1], oz = rays_o[3*ray+2];
    const float dx = rays_d[3*ray+0], dy = rays_d[3*ray+1], dz = rays_d[3*ray+2];

    {
        float px = fmaf(dx, zz.x, ox), py = fmaf(dy, zz.x, oy), pz = fmaf(dz, zz.x, oz);
        shr[2*lane] = sqrtf(px*px + py*py + pz*pz);
        px = fmaf(dx, zz.y, ox); py = fmaf(dy, zz.y, oy); pz = fmaf(dz, zz.y, oz);
        shr[2*lane+1] = sqrtf(px*px + py*py + pz*pz);
    }
    __syncwarp();

    // ---- per-interval alpha (i in [0,62]); lane handles i=2*lane, 2*lane+1 ----
    auto calc_alpha = [&](int i) -> float {
        const float zi  = shz[i],   zi1 = shz[i+1];
        const float si  = shs[i],   si1 = shs[i+1];
        float cv  = (si1 - si) / (zi1 - zi + 1e-5f);
        float pcv = (i == 0) ? 0.0f
                             : (si - shs[i-1]) / (zi - shz[i-1] + 1e-5f);
        cv = fminf(pcv, cv);
        cv = fminf(fmaxf(cv, -1000.0f), 0.0f);
        const float inside = (shr[i] < 1.0f || shr[i+1] < 1.0f) ? 1.0f : 0.0f;
        cv *= inside;
        const float mid  = 0.5f * (si + si1);
        const float dist = zi1 - zi;
        const float pe = mid - cv * dist * 0.5f;
        const float ne = mid + cv * dist * 0.5f;
        const float pc = 1.0f / (1.0f + expf(-pe * inv_s));
        const float nc = 1.0f / (1.0f + expf(-ne * inv_s));
        return (pc - nc + 1e-5f) / (pc + 1e-5f);
    };

    const float alpha0 = calc_alpha(2*lane);
    const float alpha1 = (lane < 31) ? calc_alpha(2*lane + 1) : 0.0f;

    // ---- transmittance cumprod via warp scan ----
    const float m0 = 1.0f - alpha0 + 1e-7f;
    const float m1 = (lane < 31) ? (1.0f - alpha1 + 1e-7f) : 1.0f;

    float incp = m0 * m1;
    #pragma unroll
    for (int off = 1; off < 32; off <<= 1) {
        const float v = __shfl_up_sync(0xffffffffu, incp, off);
        if (lane >= off) incp *= v;
    }
    float exclp = __shfl_up_sync(0xffffffffu, incp, 1);
    if (lane == 0) exclp = 1.0f;

    // weights (+1e-5 from sample_pdf_det)
    const float w0 = alpha0 * exclp + 1e-5f;
    const float w1 = (lane < 31) ? (alpha1 * exclp * m0 + 1e-5f) : 0.0f;

    // ---- CDF cumsum via warp scan ----
    const float lsum = w0 + w1;
    float incs = lsum;
    #pragma unroll
    for (int off = 1; off < 32; off <<= 1) {
        const float v = __shfl_up_sync(0xffffffffu, incs, off);
        if (lane >= off) incs += v;
    }
    const float total = __shfl_sync(0xffffffffu, incs, 31);
    float exs = __shfl_up_sync(0xffffffffu, incs, 1);
    if (lane == 0) exs = 0.0f;

    const float rtot = 1.0f / total;
    if (lane == 0) shc[0] = 0.0f;
    shc[2*lane + 1] = (exs + w0) * rtot;
    if (lane < 31) shc[2*lane + 2] = (exs + w0 + w1) * rtot;
    __syncwarp();

    // ---- inverse-CDF sampling: u_j = (j + 0.5)/64, searchsorted side='right' ----
    auto samp = [&](int j) -> float {
        const float u = ((float)j + 0.5f) * 0.015625f;
        int lo = 0, hi = NS;            // insertion index in [0, 64]
        while (lo < hi) {
            const int mid = (lo + hi) >> 1;
            if (shc[mid] <= u) lo = mid + 1;
            else               hi = mid;
        }
        const int below = max(lo - 1, 0);
        const int above = min(lo, NS - 1);
        const float cb = shc[below], ca = shc[above];
        const float bb = shz[below], ba = shz[above];
        float den = ca - cb;
        if (den < 1e-5f) den = 1.0f;
        const float t = (u - cb) / den;
        return bb + t * (ba - bb);
    };

    const float r0 = samp(2*lane);
    const float r1 = samp(2*lane + 1);
    reinterpret_cast<float2*>(out + base)[lane] = make_float2(r0, r1);
}

extern "C" void kernel_launch(void* const* d_in, const int* in_sizes, int n_in,
                              void* d_out, int out_size) {
    const float* rays_o = (const float*)d_in[0];
    const float* rays_d = (const float*)d_in[1];
    const float* z_vals = (const float*)d_in[2];
    const float* sdf    = (const float*)d_in[3];
    // n_importance = 64, inv_s = 64 — fixed by setup_inputs()
    const int n_rays = in_sizes[0] / 3;
    const int blocks = (n_rays + WARPS_PER_BLOCK - 1) / WARPS_PER_BLOCK;
    neus_kernel<<<blocks, WARPS_PER_BLOCK * 32>>>(
        rays_o, rays_d, z_vals, sdf, (float*)d_out, n_rays, 64.0f);
}

// round 2
// speedup vs baseline: 1.6437x; 1.6437x over previous
#include <cuda_runtime.h>
#include <math.h>

// NeuS importance sampling: one warp per ray, 2 samples per lane.
// N_RAYS = 131072, N_SAMPLES = 64, N_IMP = 64, inv_s = 64.
// Round 2: branchless search, shuffle-based alpha phase, fast-math intrinsics.

#define WARPS_PER_BLOCK 8
#define NS 64

__global__ __launch_bounds__(WARPS_PER_BLOCK * 32)
void neus_kernel(const float* __restrict__ rays_o,
                 const float* __restrict__ rays_d,
                 const float* __restrict__ z_vals,
                 const float* __restrict__ sdf,
                 float* __restrict__ out,
                 int n_rays, float inv_s)
{
    const int wib  = threadIdx.x >> 5;
    const int lane = threadIdx.x & 31;
    const int ray  = blockIdx.x * WARPS_PER_BLOCK + wib;
    if (ray >= n_rays) return;   // whole warp exits together

    __shared__ float sh_c[WARPS_PER_BLOCK][NS];   // normalized CDF, entries 0..63
    __shared__ float sh_z[WARPS_PER_BLOCK][NS];   // z bins
    float* shc = sh_c[wib];
    float* shz = sh_z[wib];

    // ---- coalesced float2 loads: lane owns samples 2l, 2l+1 ----
    const size_t base = (size_t)ray * NS;
    const float2 zz = reinterpret_cast<const float2*>(z_vals + base)[lane];
    const float2 ss = reinterpret_cast<const float2*>(sdf    + base)[lane];

    const float ox = rays_o[3*ray+0], oy = rays_o[3*ray+1], oz = rays_o[3*ray+2];
    const float dx = rays_d[3*ray+0], dy = rays_d[3*ray+1], dz = rays_d[3*ray+2];

    // squared radii (no sqrt: only r<1 is ever needed)
    float px = fmaf(dx, zz.x, ox), py = fmaf(dy, zz.x, oy), pz = fmaf(dz, zz.x, oz);
    const float r2_0 = fmaf(px, px, fmaf(py, py, pz*pz));
    px = fmaf(dx, zz.y, ox); py = fmaf(dy, zz.y, oy); pz = fmaf(dz, zz.y, oz);
    const float r2_1 = fmaf(px, px, fmaf(py, py, pz*pz));

    // neighbor (lane+1).x values = element 2l+2
    const float z2   = __shfl_down_sync(0xffffffffu, zz.x, 1);
    const float s2   = __shfl_down_sync(0xffffffffu, ss.x, 1);
    const float r2_2 = __shfl_down_sync(0xffffffffu, r2_0, 1);

    // cos_val per interval, computed ONCE each, shared via shuffle
    const float d0 = __fdividef(ss.y - ss.x, zz.y - zz.x + 1e-5f);   // interval 2l
    const float d1 = __fdividef(s2  - ss.y, z2  - zz.y + 1e-5f);     // interval 2l+1 (lane31: junk, masked)
    float dprev = __shfl_up_sync(0xffffffffu, d1, 1);                // cos of interval 2l-1
    if (lane == 0) dprev = 0.0f;

    float cv0 = fminf(dprev, d0);
    float cv1 = fminf(d0, d1);
    cv0 = fminf(fmaxf(cv0, -1000.0f), 0.0f);
    cv1 = fminf(fmaxf(cv1, -1000.0f), 0.0f);
    if (!(r2_0 < 1.0f || r2_1 < 1.0f)) cv0 = 0.0f;
    if (!(r2_1 < 1.0f || r2_2 < 1.0f)) cv1 = 0.0f;

    // alpha from sigmoid CDFs (fast exp/div; accuracy budget is ~1e-3)
    const float mid0  = 0.5f * (ss.x + ss.y), hd0 = 0.5f * (zz.y - zz.x);
    const float mid1  = 0.5f * (ss.y + s2),   hd1 = 0.5f * (z2 - zz.y);
    const float pe0 = mid0 - cv0 * hd0, ne0 = mid0 + cv0 * hd0;
    const float pe1 = mid1 - cv1 * hd1, ne1 = mid1 + cv1 * hd1;

    const float pc0 = __fdividef(1.0f, 1.0f + __expf(-pe0 * inv_s));
    const float nc0 = __fdividef(1.0f, 1.0f + __expf(-ne0 * inv_s));
    const float pc1 = __fdividef(1.0f, 1.0f + __expf(-pe1 * inv_s));
    const float nc1 = __fdividef(1.0f, 1.0f + __expf(-ne1 * inv_s));

    const float alpha0 = __fdividef(pc0 - nc0 + 1e-5f, pc0 + 1e-5f);
    float alpha1       = __fdividef(pc1 - nc1 + 1e-5f, pc1 + 1e-5f);
    if (lane == 31) alpha1 = 0.0f;

    // ---- transmittance cumprod (exclusive) via warp scan ----
    const float m0 = 1.0f - alpha0 + 1e-7f;
    const float m1 = (lane < 31) ? (1.0f - alpha1 + 1e-7f) : 1.0f;

    float incp = m0 * m1;
    #pragma unroll
    for (int off = 1; off < 32; off <<= 1) {
        const float v = __shfl_up_sync(0xffffffffu, incp, off);
        if (lane >= off) incp *= v;
    }
    float exclp = __shfl_up_sync(0xffffffffu, incp, 1);
    if (lane == 0) exclp = 1.0f;

    const float w0 = fmaf(alpha0, exclp, 1e-5f);
    const float w1 = (lane < 31) ? fmaf(alpha1, exclp * m0, 1e-5f) : 0.0f;

    // ---- CDF cumsum via warp scan ----
    const float lsum = w0 + w1;
    float incs = lsum;
    #pragma unroll
    for (int off = 1; off < 32; off <<= 1) {
        const float v = __shfl_up_sync(0xffffffffu, incs, off);
        if (lane >= off) incs += v;
    }
    const float total = __shfl_sync(0xffffffffu, incs, 31);
    float exs = __shfl_up_sync(0xffffffffu, incs, 1);
    if (lane == 0) exs = 0.0f;

    const float rtot = __fdividef(1.0f, total);
    // shc[i] = normalized cdf[i] (prefix before interval i); shc[0] = 0
    if (lane == 0) shc[0] = 0.0f;
    shc[2*lane + 1] = (exs + w0) * rtot;
    if (lane < 31) shc[2*lane + 2] = (exs + lsum) * rtot;
    shz[2*lane]     = zz.x;
    shz[2*lane + 1] = zz.y;
    __syncwarp();

    // ---- inverse-CDF sampling: branchless uniform binary search ----
    // idx = largest k in [0,63] with cdf[k] <= u   (side='right' semantics)
    auto samp = [&](float u) -> float {
        int idx = 0;
        #pragma unroll
        for (int step = 32; step >= 1; step >>= 1)
            idx += (shc[idx + step] <= u) ? step : 0;
        const int above = min(idx + 1, NS - 1);
        const float cb = shc[idx], ca = shc[above];
        const float bb = shz[idx], ba = shz[above];
        float den = ca - cb;
        if (den < 1e-5f) den = 1.0f;
        const float t = __fdividef(u - cb, den);
        return fmaf(t, ba - bb, bb);
    };

    const float u0 = ((float)(2*lane)     + 0.5f) * 0.015625f;
    const float u1 = ((float)(2*lane + 1) + 0.5f) * 0.015625f;
    reinterpret_cast<float2*>(out + base)[lane] = make_float2(samp(u0), samp(u1));
}

extern "C" void kernel_launch(void* const* d_in, const int* in_sizes, int n_in,
                              void* d_out, int out_size) {
    const float* rays_o = (const float*)d_in[0];
    const float* rays_d = (const float*)d_in[1];
    const float* z_vals = (const float*)d_in[2];
    const float* sdf    = (const float*)d_in[3];
    const int n_rays = in_sizes[0] / 3;
    const int blocks = (n_rays + WARPS_PER_BLOCK - 1) / WARPS_PER_BLOCK;
    neus_kernel<<<blocks, WARPS_PER_BLOCK * 32>>>(
        rays_o, rays_d, z_vals, sdf, (float*)d_out, n_rays, 64.0f);
}